// round 2
// baseline (speedup 1.0000x reference)
#include <cuda_runtime.h>
#include <math.h>

#define NJ 30000
#define NS 12000
#define EJS 300000
#define ESJ 300000
#define ESS 150000
#define ESS2 (ESS + NS)   // + self loops = 162000
#define SBERT 384
#define HID 128
#define NH 2
#define HH (NH * HID)     // 256

// ---------------- scratch (allocation-free: __device__ globals) ----------------
__device__ __align__(16) float g_xj[NJ * HID];
__device__ __align__(16) float g_xs[NS * HID];
__device__ __align__(16) float g_hs[NJ * HH];
__device__ __align__(16) float g_oj[NJ * HH];
__device__ __align__(16) float g_os[NS * HH];
__device__ __align__(16) float g_alps[NJ * NH];
__device__ __align__(16) float g_alpd[NJ * NH];
__device__ __align__(16) unsigned g_m[NJ * NH];
__device__ __align__(16) float g_den[NJ * NH];
__device__ __align__(16) float g_e[EJS * NH];
__device__ __align__(16) int g_sss[ESS2];
__device__ __align__(16) int g_ssd[ESS2];
__device__ __align__(16) float g_q[HID];

// ---------------- helpers ----------------
__device__ __forceinline__ float wred(float v) {
#pragma unroll
    for (int o = 16; o > 0; o >>= 1) v += __shfl_xor_sync(0xffffffffu, v, o);
    return v;
}

// order-preserving float<->uint encoding for atomicMax segment-max
__device__ __forceinline__ unsigned fenc(float f) {
    unsigned u = __float_as_uint(f);
    return (u & 0x80000000u) ? ~u : (u | 0x80000000u);
}
__device__ __forceinline__ float fdec(unsigned u) {
    return (u & 0x80000000u) ? __uint_as_float(u & 0x7fffffffu) : __uint_as_float(~u);
}

// ---------------- generic tiled SGEMM, N_cols per block = 128 ----------------
// block dim (32,8); block tile 32 rows x 128 cols; per-thread 4x4.
// grid.y = head (column-tile) when output has 2*128 cols.
#define EPI_BIAS_RELU 1
#define EPI_LN_RELU 2
#define EPI_ALPHA_STORE 3
#define EPI_ALPHA_ONLY 4
#define EPI_BIAS_STORE 5

template <int EPI>
__global__ void gemm_k(const float* __restrict__ A, int lda,
                       const float* __restrict__ B0, int ldb,
                       float* __restrict__ C0, int ldc,
                       int N, int K,
                       const float* __restrict__ bias,
                       const float* __restrict__ gamma, const float* __restrict__ beta,
                       const float* __restrict__ avec0, float* __restrict__ alpha) {
    const int head = blockIdx.y;
    const float* B = B0 + head * HID;
    float* C = C0 ? (C0 + head * HID) : C0;

    const int tx = threadIdx.x, ty = threadIdx.y;
    const int tid = ty * 32 + tx;
    const int row0 = blockIdx.x * 32;

    __shared__ float As[16][33];
    __shared__ __align__(16) float Bs[16][128];

    float acc[4][4];
#pragma unroll
    for (int i = 0; i < 4; i++)
#pragma unroll
        for (int j = 0; j < 4; j++) acc[i][j] = 0.f;

    for (int k0 = 0; k0 < K; k0 += 16) {
        // A tile: 32 rows x 16 k, float2 per thread
        {
            int r = tid >> 3, kp = tid & 7;
            int grow = row0 + r;
            float2 v = make_float2(0.f, 0.f);
            if (grow < N) v = *(const float2*)(A + (size_t)grow * lda + k0 + kp * 2);
            As[kp * 2][r] = v.x;
            As[kp * 2 + 1][r] = v.y;
        }
        // B tile: 16 x 128, 2x float4 per thread
        {
#pragma unroll
            for (int l = 0; l < 2; l++) {
                int idx = tid + l * 256;
                int br = idx >> 5, bc = idx & 31;
                float4 v = *(const float4*)(B + (size_t)(k0 + br) * ldb + bc * 4);
                *(float4*)&Bs[br][bc * 4] = v;
            }
        }
        __syncthreads();
#pragma unroll
        for (int k = 0; k < 16; k++) {
            float a0 = As[k][ty], a1 = As[k][ty + 8], a2 = As[k][ty + 16], a3 = As[k][ty + 24];
            float b0 = Bs[k][tx], b1 = Bs[k][tx + 32], b2 = Bs[k][tx + 64], b3 = Bs[k][tx + 96];
            acc[0][0] += a0 * b0; acc[0][1] += a0 * b1; acc[0][2] += a0 * b2; acc[0][3] += a0 * b3;
            acc[1][0] += a1 * b0; acc[1][1] += a1 * b1; acc[1][2] += a1 * b2; acc[1][3] += a1 * b3;
            acc[2][0] += a2 * b0; acc[2][1] += a2 * b1; acc[2][2] += a2 * b2; acc[2][3] += a2 * b3;
            acc[3][0] += a3 * b0; acc[3][1] += a3 * b1; acc[3][2] += a3 * b2; acc[3][3] += a3 * b3;
        }
        __syncthreads();
    }

    // --------- epilogue ---------
    if (EPI == EPI_LN_RELU) {
#pragma unroll
        for (int i = 0; i < 4; i++) {
            int grow = row0 + ty + 8 * i;
            float v[4], s = 0.f, s2 = 0.f;
#pragma unroll
            for (int j = 0; j < 4; j++) {
                int c = tx + 32 * j;
                v[j] = acc[i][j] + bias[c];
                s += v[j];
                s2 += v[j] * v[j];
            }
            s = wred(s);
            s2 = wred(s2);
            float mu = s * (1.0f / 128.0f);
            float var = s2 * (1.0f / 128.0f) - mu * mu;
            float rs = rsqrtf(var + 1e-5f);
            if (grow < N) {
#pragma unroll
                for (int j = 0; j < 4; j++) {
                    int c = tx + 32 * j;
                    float o = (v[j] - mu) * rs * gamma[c] + beta[c];
                    C[(size_t)grow * ldc + c] = fmaxf(o, 0.f);
                }
            }
        }
    } else if (EPI == EPI_ALPHA_STORE || EPI == EPI_ALPHA_ONLY) {
        const float* av = avec0 + head * HID;
#pragma unroll
        for (int i = 0; i < 4; i++) {
            int grow = row0 + ty + 8 * i;
            float s = 0.f;
#pragma unroll
            for (int j = 0; j < 4; j++) {
                int c = tx + 32 * j;
                s += acc[i][j] * av[c];
            }
            s = wred(s);
            if (grow < N) {
                if (EPI == EPI_ALPHA_STORE) {
#pragma unroll
                    for (int j = 0; j < 4; j++) {
                        int c = tx + 32 * j;
                        C[(size_t)grow * ldc + c] = acc[i][j];
                    }
                }
                if (tx == 0) alpha[grow * NH + head] = s;
            }
        }
    } else {  // EPI_BIAS_RELU / EPI_BIAS_STORE
#pragma unroll
        for (int i = 0; i < 4; i++) {
            int grow = row0 + ty + 8 * i;
            if (grow < N) {
#pragma unroll
                for (int j = 0; j < 4; j++) {
                    int c = tx + 32 * j;
                    float o = acc[i][j] + bias[c];
                    if (EPI == EPI_BIAS_RELU) o = fmaxf(o, 0.f);
                    C[(size_t)grow * ldc + c] = o;
                }
            }
        }
    }
}

// ---------------- small kernels ----------------
__global__ void build_ss(const int* __restrict__ s_in, const int* __restrict__ d_in,
                         int* __restrict__ s_out, int* __restrict__ d_out) {
    int i = blockIdx.x * blockDim.x + threadIdx.x;
    if (i >= ESS2) return;
    if (i < ESS) {
        s_out[i] = s_in[i];
        d_out[i] = d_in[i];
    } else {
        s_out[i] = i - ESS;
        d_out[i] = i - ESS;
    }
}

__global__ void fill_bias(float* __restrict__ out, const float* __restrict__ b1,
                          const float* __restrict__ b2, int n) {
    int i = blockIdx.x * blockDim.x + threadIdx.x;
    if (i >= n) return;
    int c = i & (HH - 1);
    float v = b1[c];
    if (b2) v += b2[c];
    out[i] = v;
}

__global__ void init_md(unsigned* __restrict__ m, float* __restrict__ den, int n) {
    int i = blockIdx.x * blockDim.x + threadIdx.x;
    if (i < n) {
        m[i] = 0u;  // below every real encoding
        den[i] = 0.f;
    }
}

__global__ void edge_e_max(const int* __restrict__ src, const int* __restrict__ dst,
                           const float* __restrict__ als, const float* __restrict__ ald,
                           float* __restrict__ e, unsigned* __restrict__ m, int E) {
    int i = blockIdx.x * blockDim.x + threadIdx.x;
    if (i >= E) return;
    int s = src[i], d = dst[i];
#pragma unroll
    for (int h = 0; h < NH; h++) {
        float v = als[s * NH + h] + ald[d * NH + h];
        v = v > 0.f ? v : 0.2f * v;  // leaky relu 0.2
        e[i * NH + h] = v;
        atomicMax(&m[d * NH + h], fenc(v));
    }
}

__global__ void edge_p_den(const int* __restrict__ dst, float* __restrict__ e,
                           const unsigned* __restrict__ m, float* __restrict__ den, int E) {
    int i = blockIdx.x * blockDim.x + threadIdx.x;
    if (i >= E) return;
    int d = dst[i];
#pragma unroll
    for (int h = 0; h < NH; h++) {
        float mx = fdec(m[d * NH + h]);
        float p = expf(e[i * NH + h] - mx);
        e[i * NH + h] = p;
        atomicAdd(&den[d * NH + h], p);
    }
}

// 64 threads per edge; each thread handles 4 channels (float4) of the 256-wide row.
__global__ void edge_scatter(const int* __restrict__ src, const int* __restrict__ dst,
                             const float* __restrict__ p, const float* __restrict__ den,
                             const float* __restrict__ hs, float* __restrict__ out, int E) {
    int i = blockIdx.x * blockDim.x + threadIdx.x;
    int edge = i >> 6;
    if (edge >= E) return;
    int lane = i & 63;
    int h = lane >> 5;
    int s = src[edge], d = dst[edge];
    float w = p[edge * NH + h] / (den[d * NH + h] + 1e-16f);
    float4 v = ((const float4*)(hs + (size_t)s * HH))[lane];
    float* o = out + (size_t)d * HH + lane * 4;
    atomicAdd(o + 0, v.x * w);
    atomicAdd(o + 1, v.y * w);
    atomicAdd(o + 2, v.z * w);
    atomicAdd(o + 3, v.w * w);
}

__global__ void qkern(const float* __restrict__ query, const float* __restrict__ Wq,
                      const float* __restrict__ bq, float* __restrict__ qout,
                      float* __restrict__ qout2) {
    __shared__ float qs[SBERT];
    int t = threadIdx.x;
    for (int k = t; k < SBERT; k += 128) qs[k] = query[k];
    __syncthreads();
    float acc = bq[t];
    for (int k = 0; k < SBERT; k++) acc += qs[k] * Wq[k * HID + t];
    qout[t] = acc;
    qout2[t] = acc;
}

__global__ void scores_kern(const float* __restrict__ emb, const float* __restrict__ q,
                            float* __restrict__ sc) {
    __shared__ float qs[HID];
    int t = threadIdx.x;
    if (t < HID) qs[t] = q[t];
    __syncthreads();
    int w = t >> 5, lane = t & 31;
    int row = blockIdx.x * 8 + w;
    if (row >= NJ) return;
    float4 v = ((const float4*)(emb + (size_t)row * HID))[lane];
    float s = v.x * qs[lane * 4] + v.y * qs[lane * 4 + 1] + v.z * qs[lane * 4 + 2] +
              v.w * qs[lane * 4 + 3];
    s = wred(s);
    if (lane == 0) sc[row] = s;
}

// ---------------- launcher ----------------
extern "C" void kernel_launch(void* const* d_in, const int* in_sizes, int n_in,
                              void* d_out, int out_size) {
    const float* x_job = (const float*)d_in[0];
    const float* x_skill = (const float*)d_in[1];
    const int* js_s = (const int*)d_in[2];
    const int* js_d = (const int*)d_in[3];
    const int* sj_s = (const int*)d_in[4];
    const int* sj_d = (const int*)d_in[5];
    const int* ss_s = (const int*)d_in[6];
    const int* ss_d = (const int*)d_in[7];
    const float* query = (const float*)d_in[8];
    const float* W0j = (const float*)d_in[9];
    const float* b0j = (const float*)d_in[10];
    const float* g0j = (const float*)d_in[11];
    const float* be0j = (const float*)d_in[12];
    const float* W0s = (const float*)d_in[13];
    const float* b0s = (const float*)d_in[14];
    const float* g0s = (const float*)d_in[15];
    const float* be0s = (const float*)d_in[16];
    const float* gWs = (const float*)d_in[17];
    const float* gWd = (const float*)d_in[18];
    const float* gas = (const float*)d_in[19];
    const float* gad = (const float*)d_in[20];
    const float* gb = (const float*)d_in[21];
    const float* iW = (const float*)d_in[22];
    const float* ib = (const float*)d_in[23];
    const float* Wjf = (const float*)d_in[24];
    const float* bjf = (const float*)d_in[25];
    const float* Wq = (const float*)d_in[26];
    const float* bq = (const float*)d_in[27];

    float* out = (float*)d_out;
    float* scores = out;                // [NJ]
    float* emb = out + NJ;              // [NJ, 128]
    float* qout = out + NJ + NJ * HID;  // [128]

    float *p_xj, *p_xs, *p_hs, *p_oj, *p_os, *p_as, *p_ad, *p_den, *p_e, *p_q;
    unsigned* p_m;
    int *p_sss, *p_ssd;
    cudaGetSymbolAddress((void**)&p_xj, g_xj);
    cudaGetSymbolAddress((void**)&p_xs, g_xs);
    cudaGetSymbolAddress((void**)&p_hs, g_hs);
    cudaGetSymbolAddress((void**)&p_oj, g_oj);
    cudaGetSymbolAddress((void**)&p_os, g_os);
    cudaGetSymbolAddress((void**)&p_as, g_alps);
    cudaGetSymbolAddress((void**)&p_ad, g_alpd);
    cudaGetSymbolAddress((void**)&p_m, g_m);
    cudaGetSymbolAddress((void**)&p_den, g_den);
    cudaGetSymbolAddress((void**)&p_e, g_e);
    cudaGetSymbolAddress((void**)&p_q, g_q);
    cudaGetSymbolAddress((void**)&p_sss, g_sss);
    cudaGetSymbolAddress((void**)&p_ssd, g_ssd);

    dim3 blk(32, 8);

    // initial per-type lin + LN + relu
    gemm_k<EPI_LN_RELU><<<dim3((NJ + 31) / 32, 1), blk>>>(
        x_job, SBERT, W0j, HID, p_xj, HID, NJ, SBERT, b0j, g0j, be0j, nullptr, nullptr);
    gemm_k<EPI_LN_RELU><<<dim3((NS + 31) / 32, 1), blk>>>(
        x_skill, SBERT, W0s, HID, p_xs, HID, NS, SBERT, b0s, g0s, be0s, nullptr, nullptr);
    build_ss<<<(ESS2 + 255) / 256, 256>>>(ss_s, ss_d, p_sss, p_ssd);

    auto rel = [&](int L, int r, const float* xsrc, int Nsrc, const float* xdst, int Ndst,
                   const int* src, const int* dst, int E, float* outbuf) {
        size_t wofs = (size_t)(L * 3 + r) * HID * HH;
        const float* Ws = gWs + wofs;
        const float* Wd = gWd + wofs;
        const float* as_v = gas + (size_t)(L * 3 + r) * NH * HID;
        const float* ad_v = gad + (size_t)(L * 3 + r) * NH * HID;
        init_md<<<(Ndst * NH + 255) / 256, 256>>>(p_m, p_den, Ndst * NH);
        gemm_k<EPI_ALPHA_STORE><<<dim3((Nsrc + 31) / 32, NH), blk>>>(
            xsrc, HID, Ws, HH, p_hs, HH, Nsrc, HID, nullptr, nullptr, nullptr, as_v, p_as);
        gemm_k<EPI_ALPHA_ONLY><<<dim3((Ndst + 31) / 32, NH), blk>>>(
            xdst, HID, Wd, HH, nullptr, HH, Ndst, HID, nullptr, nullptr, nullptr, ad_v, p_ad);
        edge_e_max<<<(E + 255) / 256, 256>>>(src, dst, p_as, p_ad, p_e, p_m, E);
        edge_p_den<<<(E + 255) / 256, 256>>>(dst, p_e, p_m, p_den, E);
        edge_scatter<<<(E * 64 + 255) / 256, 256>>>(src, dst, p_e, p_den, p_hs, outbuf, E);
    };

    for (int L = 0; L < 2; L++) {
        const float* b_js = gb + (size_t)(L * 3 + 0) * HH;
        const float* b_sj = gb + (size_t)(L * 3 + 1) * HH;
        const float* b_ss = gb + (size_t)(L * 3 + 2) * HH;
        // out buffers pre-filled with biases (HeteroConv sum adds both skill-relation biases)
        fill_bias<<<(NS * HH + 255) / 256, 256>>>(p_os, b_js, b_ss, NS * HH);
        fill_bias<<<(NJ * HH + 255) / 256, 256>>>(p_oj, b_sj, nullptr, NJ * HH);

        rel(L, 0, p_xj, NJ, p_xs, NS, js_s, js_d, EJS, p_os);   // job -> skill
        rel(L, 2, p_xs, NS, p_xs, NS, p_sss, p_ssd, ESS2, p_os);  // skill -> skill (+loops)
        rel(L, 1, p_xs, NS, p_xj, NJ, sj_s, sj_d, ESJ, p_oj);   // skill -> job

        // inter linears + relu
        gemm_k<EPI_BIAS_RELU><<<dim3((NJ + 31) / 32, 1), blk>>>(
            p_oj, HH, iW + (size_t)(L * 2 + 0) * HH * HID, HID, p_xj, HID, NJ, HH,
            ib + (size_t)(L * 2 + 0) * HID, nullptr, nullptr, nullptr, nullptr);
        gemm_k<EPI_BIAS_RELU><<<dim3((NS + 31) / 32, 1), blk>>>(
            p_os, HH, iW + (size_t)(L * 2 + 1) * HH * HID, HID, p_xs, HID, NS, HH,
            ib + (size_t)(L * 2 + 1) * HID, nullptr, nullptr, nullptr, nullptr);
    }

    // job_emb = xj @ Wjf + bjf  -> directly into d_out
    gemm_k<EPI_BIAS_STORE><<<dim3((NJ + 31) / 32, 1), blk>>>(
        p_xj, HID, Wjf, HID, emb, HID, NJ, HID, bjf, nullptr, nullptr, nullptr, nullptr);
    // q = query @ Wq + bq
    qkern<<<1, 128>>>(query, Wq, bq, qout, p_q);
    // scores = job_emb @ q
    scores_kern<<<(NJ + 7) / 8, 256>>>(emb, p_q, scores);
}

// round 3
// speedup vs baseline: 2.0310x; 2.0310x over previous
#include <cuda_runtime.h>
#include <math.h>

#define NJ 30000
#define NS 12000
#define EJS 300000
#define ESJ 300000
#define ESS 150000
#define ESS2 (ESS + NS)   // + self loops = 162000
#define SBERT 384
#define HID 128
#define NH 2
#define HH (NH * HID)     // 256

typedef unsigned long long ull;

// ---------------- scratch (allocation-free: __device__ globals) ----------------
__device__ __align__(16) float g_xj[NJ * HID];
__device__ __align__(16) float g_xs[NS * HID];
__device__ __align__(16) float g_hs[NJ * HH];
__device__ __align__(16) float g_oj[NJ * HH];
__device__ __align__(16) float g_os[NS * HH];
__device__ __align__(16) float g_als[NJ * NH];
__device__ __align__(16) float g_ald[NJ * NH];
__device__ __align__(16) float g_wdeff[6 * HID * NH];
__device__ __align__(16) float g_q[HID];
// CSR
__device__ int g_cnt[NJ];
__device__ int g_cur[NJ];
__device__ int g_rp_js[NS + 1];
__device__ int g_rp_ss[NS + 1];
__device__ int g_rp_sj[NJ + 1];
__device__ int g_cs_js[EJS];
__device__ int g_cs_ss[ESS2];
__device__ int g_cs_sj[ESJ];

// ---------------- helpers ----------------
__device__ __forceinline__ float wred(float v) {
#pragma unroll
    for (int o = 16; o > 0; o >>= 1) v += __shfl_xor_sync(0xffffffffu, v, o);
    return v;
}

#define FMA2(c, a, b) asm("fma.rn.f32x2 %0, %1, %2, %0;" : "+l"(c) : "l"(a), "l"(b))

// ---------------- f32x2 tiled SGEMM: block tile 32x128, per-thread 4 rows x 4 cols ----
// cols per thread: tx*2, tx*2+1, tx*2+64, tx*2+65. grid.y = head (col tile of 128).
#define EPI_BIAS_RELU 1
#define EPI_LN_RELU 2
#define EPI_ALPHA_STORE 3
#define EPI_BIAS_STORE 5

template <int EPI>
__global__ void gemm_k(const float* __restrict__ A, int lda,
                       const float* __restrict__ B0, int ldb,
                       float* __restrict__ C0, int ldc,
                       int N, int K,
                       const float* __restrict__ bias,
                       const float* __restrict__ gamma, const float* __restrict__ beta,
                       const float* __restrict__ avec0, float* __restrict__ alpha) {
    const int head = blockIdx.y;
    const float* B = B0 + head * HID;
    float* C = C0 ? (C0 + head * HID) : C0;

    const int tx = threadIdx.x, ty = threadIdx.y;
    const int tid = ty * 32 + tx;
    const int row0 = blockIdx.x * 32;

    __shared__ float2 As2[16][33];                 // duplicated A: (a,a)
    __shared__ __align__(16) float Bs[16][128];

    ull acc[4][2];
#pragma unroll
    for (int i = 0; i < 4; i++) { acc[i][0] = 0ull; acc[i][1] = 0ull; }

    for (int k0 = 0; k0 < K; k0 += 16) {
        {   // A tile: 32 rows x 16 k
            int r = tid >> 3, kp = tid & 7;
            int grow = row0 + r;
            float2 v = make_float2(0.f, 0.f);
            if (grow < N) v = *(const float2*)(A + (size_t)grow * lda + k0 + kp * 2);
            As2[kp * 2][r] = make_float2(v.x, v.x);
            As2[kp * 2 + 1][r] = make_float2(v.y, v.y);
        }
        {   // B tile: 16 x 128
#pragma unroll
            for (int l = 0; l < 2; l++) {
                int idx = tid + l * 256;
                int br = idx >> 5, bc = idx & 31;
                float4 v = *(const float4*)(B + (size_t)(k0 + br) * ldb + bc * 4);
                *(float4*)&Bs[br][bc * 4] = v;
            }
        }
        __syncthreads();
#pragma unroll
        for (int k = 0; k < 16; k++) {
            ull a0 = *(const ull*)&As2[k][ty];
            ull a1 = *(const ull*)&As2[k][ty + 8];
            ull a2 = *(const ull*)&As2[k][ty + 16];
            ull a3 = *(const ull*)&As2[k][ty + 24];
            ull b0 = *(const ull*)&Bs[k][tx * 2];
            ull b1 = *(const ull*)&Bs[k][tx * 2 + 64];
            FMA2(acc[0][0], a0, b0); FMA2(acc[0][1], a0, b1);
            FMA2(acc[1][0], a1, b0); FMA2(acc[1][1], a1, b1);
            FMA2(acc[2][0], a2, b0); FMA2(acc[2][1], a2, b1);
            FMA2(acc[3][0], a3, b0); FMA2(acc[3][1], a3, b1);
        }
        __syncthreads();
    }

    const int c0 = tx * 2;
    // --------- epilogue ---------
    if (EPI == EPI_LN_RELU) {
#pragma unroll
        for (int i = 0; i < 4; i++) {
            int grow = row0 + ty + 8 * i;
            float2 p0 = *(float2*)&acc[i][0];
            float2 p1 = *(float2*)&acc[i][1];
            float v[4];
            v[0] = p0.x + bias[c0];      v[1] = p0.y + bias[c0 + 1];
            v[2] = p1.x + bias[c0 + 64]; v[3] = p1.y + bias[c0 + 65];
            float s = v[0] + v[1] + v[2] + v[3];
            float s2 = v[0]*v[0] + v[1]*v[1] + v[2]*v[2] + v[3]*v[3];
            s = wred(s); s2 = wred(s2);
            float mu = s * (1.0f / 128.0f);
            float var = s2 * (1.0f / 128.0f) - mu * mu;
            float rs = rsqrtf(var + 1e-5f);
            if (grow < N) {
                float o0 = fmaxf((v[0]-mu)*rs*gamma[c0] + beta[c0], 0.f);
                float o1 = fmaxf((v[1]-mu)*rs*gamma[c0+1] + beta[c0+1], 0.f);
                float o2 = fmaxf((v[2]-mu)*rs*gamma[c0+64] + beta[c0+64], 0.f);
                float o3 = fmaxf((v[3]-mu)*rs*gamma[c0+65] + beta[c0+65], 0.f);
                *(float2*)(C + (size_t)grow * ldc + c0) = make_float2(o0, o1);
                *(float2*)(C + (size_t)grow * ldc + c0 + 64) = make_float2(o2, o3);
            }
        }
    } else if (EPI == EPI_ALPHA_STORE) {
        const float* av = avec0 + head * HID;
#pragma unroll
        for (int i = 0; i < 4; i++) {
            int grow = row0 + ty + 8 * i;
            float2 p0 = *(float2*)&acc[i][0];
            float2 p1 = *(float2*)&acc[i][1];
            float s = p0.x*av[c0] + p0.y*av[c0+1] + p1.x*av[c0+64] + p1.y*av[c0+65];
            s = wred(s);
            if (grow < N) {
                *(float2*)(C + (size_t)grow * ldc + c0) = p0;
                *(float2*)(C + (size_t)grow * ldc + c0 + 64) = p1;
                if (tx == 0) alpha[grow * NH + head] = s;
            }
        }
    } else {  // EPI_BIAS_RELU / EPI_BIAS_STORE
#pragma unroll
        for (int i = 0; i < 4; i++) {
            int grow = row0 + ty + 8 * i;
            if (grow < N) {
                float2 p0 = *(float2*)&acc[i][0];
                float2 p1 = *(float2*)&acc[i][1];
                float o0 = p0.x + bias[c0],      o1 = p0.y + bias[c0 + 1];
                float o2 = p1.x + bias[c0 + 64], o3 = p1.y + bias[c0 + 65];
                if (EPI == EPI_BIAS_RELU) {
                    o0 = fmaxf(o0, 0.f); o1 = fmaxf(o1, 0.f);
                    o2 = fmaxf(o2, 0.f); o3 = fmaxf(o3, 0.f);
                }
                *(float2*)(C + (size_t)grow * ldc + c0) = make_float2(o0, o1);
                *(float2*)(C + (size_t)grow * ldc + c0 + 64) = make_float2(o2, o3);
            }
        }
    }
}

// ---------------- CSR build ----------------
__global__ void count_k(const int* __restrict__ dst, int E, int Esl, int* __restrict__ cnt) {
    int i = blockIdx.x * blockDim.x + threadIdx.x;
    if (i >= Esl) return;
    int d = (i < E) ? dst[i] : (i - E);
    atomicAdd(&cnt[d], 1);
}

__global__ void scan_k(const int* __restrict__ cnt, int* __restrict__ rowptr,
                       int* __restrict__ cursor, int n) {
    __shared__ int wsum[32];
    __shared__ int carry_s;
    int tid = threadIdx.x, lane = tid & 31, wid = tid >> 5;
    if (tid == 0) carry_s = 0;
    __syncthreads();
    for (int base = 0; base < n; base += 1024) {
        int idx = base + tid;
        int v = idx < n ? cnt[idx] : 0;
        int x = v;
#pragma unroll
        for (int o = 1; o < 32; o <<= 1) {
            int y = __shfl_up_sync(0xffffffffu, x, o);
            if (lane >= o) x += y;
        }
        if (lane == 31) wsum[wid] = x;
        __syncthreads();
        if (wid == 0) {
            int s = wsum[lane];
#pragma unroll
            for (int o = 1; o < 32; o <<= 1) {
                int y = __shfl_up_sync(0xffffffffu, s, o);
                if (lane >= o) s += y;
            }
            wsum[lane] = s;
        }
        __syncthreads();
        int carry = carry_s;
        int excl = carry + (wid ? wsum[wid - 1] : 0) + x - v;
        if (idx < n) { rowptr[idx] = excl; cursor[idx] = excl; }
        __syncthreads();
        if (tid == 0) carry_s = carry + wsum[31];
        __syncthreads();
    }
    if (threadIdx.x == 0) rowptr[n] = carry_s;
}

__global__ void fill_k(const int* __restrict__ src, const int* __restrict__ dst,
                       int E, int Esl, int* __restrict__ cursor, int* __restrict__ csrsrc) {
    int i = blockIdx.x * blockDim.x + threadIdx.x;
    if (i >= Esl) return;
    int d, sv;
    if (i < E) { d = dst[i]; sv = src[i]; } else { d = i - E; sv = i - E; }
    int p = atomicAdd(&cursor[d], 1);
    csrsrc[p] = sv;
}

// ---------------- dst-alpha: ald = x_dst @ wd_eff  ([Nd,128]@[128,2]) ----------------
__global__ void wdeff_k(const float* __restrict__ Wd, const float* __restrict__ ad,
                        float* __restrict__ wdeff) {
    int rel = blockIdx.x;               // 0..5
    int k = threadIdx.x >> 1, h = threadIdx.x & 1;
    const float* W = Wd + ((size_t)rel * HID + k) * HH + h * HID;
    const float* a = ad + (size_t)(rel * NH + h) * HID;
    float s = 0.f;
    for (int c = 0; c < HID; c++) s += W[c] * a[c];
    wdeff[rel * HH + k * 2 + h] = s;
}

__global__ void alpha_dst_k(const float* __restrict__ x, const float* __restrict__ wdeff,
                            float* __restrict__ ald, int N) {
    __shared__ float2 ws[HID];
    int tx = threadIdx.x, ty = threadIdx.y;
    int tid = ty * 32 + tx;
    if (tid < HID) ws[tid] = *(const float2*)&wdeff[tid * 2];
    __syncthreads();
    int d = blockIdx.x * 8 + ty;
    if (d >= N) return;
    float4 v = ((const float4*)(x + (size_t)d * HID))[tx];
    float2 w0 = ws[tx * 4], w1 = ws[tx * 4 + 1], w2 = ws[tx * 4 + 2], w3 = ws[tx * 4 + 3];
    float s0 = v.x * w0.x + v.y * w1.x + v.z * w2.x + v.w * w3.x;
    float s1 = v.x * w0.y + v.y * w1.y + v.z * w2.y + v.w * w3.y;
    s0 = wred(s0); s1 = wred(s1);
    if (tx == 0) *(float2*)&ald[d * 2] = make_float2(s0, s1);
}

// ---------------- fused GAT gather: warp per dst, single pass, no atomics ----------------
template <bool WRITE>
__global__ void gat_gather(const int* __restrict__ rowptr, const int* __restrict__ csrsrc,
                           const float* __restrict__ als, const float* __restrict__ ald,
                           const float* __restrict__ hs,
                           const float* __restrict__ bias1, const float* __restrict__ bias2,
                           float* __restrict__ out, int Ndst) {
    int lane = threadIdx.x, ty = threadIdx.y;
    int d = blockIdx.x * 8 + ty;
    if (d >= Ndst) return;
    int beg = rowptr[d], end = rowptr[d + 1];
    float ald0 = ald[d * 2], ald1 = ald[d * 2 + 1];
    float4 a0 = make_float4(0.f, 0.f, 0.f, 0.f), a1 = a0;
    float den0 = 0.f, den1 = 0.f;
    for (int e = beg; e < end; e++) {
        int s = csrsrc[e];
        float2 al = *(const float2*)&als[s * 2];
        float e0 = al.x + ald0; e0 = e0 > 0.f ? e0 : 0.2f * e0;
        float e1 = al.y + ald1; e1 = e1 > 0.f ? e1 : 0.2f * e1;
        float p0 = __expf(e0), p1 = __expf(e1);
        const float4* hp = (const float4*)(hs + (size_t)s * HH);
        float4 v0 = hp[lane], v1 = hp[lane + 32];
        a0.x += p0 * v0.x; a0.y += p0 * v0.y; a0.z += p0 * v0.z; a0.w += p0 * v0.w;
        a1.x += p1 * v1.x; a1.y += p1 * v1.y; a1.z += p1 * v1.z; a1.w += p1 * v1.w;
        den0 += p0; den1 += p1;
    }
    float r0 = 1.f / (den0 + 1e-16f), r1 = 1.f / (den1 + 1e-16f);
    float* o0 = out + (size_t)d * HH + lane * 4;
    float* o1 = o0 + HID;
    if (WRITE) {
        int c = lane * 4;
        float4 b0, b1;
        b0 = *(const float4*)&bias1[c];      b1 = *(const float4*)&bias1[c + HID];
        if (bias2) {
            float4 t0 = *(const float4*)&bias2[c], t1 = *(const float4*)&bias2[c + HID];
            b0.x += t0.x; b0.y += t0.y; b0.z += t0.z; b0.w += t0.w;
            b1.x += t1.x; b1.y += t1.y; b1.z += t1.z; b1.w += t1.w;
        }
        *(float4*)o0 = make_float4(b0.x + a0.x*r0, b0.y + a0.y*r0, b0.z + a0.z*r0, b0.w + a0.w*r0);
        *(float4*)o1 = make_float4(b1.x + a1.x*r1, b1.y + a1.y*r1, b1.z + a1.z*r1, b1.w + a1.w*r1);
    } else {
        float4 c0 = *(float4*)o0, c1 = *(float4*)o1;
        *(float4*)o0 = make_float4(c0.x + a0.x*r0, c0.y + a0.y*r0, c0.z + a0.z*r0, c0.w + a0.w*r0);
        *(float4*)o1 = make_float4(c1.x + a1.x*r1, c1.y + a1.y*r1, c1.z + a1.z*r1, c1.w + a1.w*r1);
    }
}

// ---------------- tail kernels ----------------
__global__ void qkern(const float* __restrict__ query, const float* __restrict__ Wq,
                      const float* __restrict__ bq, float* __restrict__ qout,
                      float* __restrict__ qout2) {
    __shared__ float qs[SBERT];
    int t = threadIdx.x;
    for (int k = t; k < SBERT; k += 128) qs[k] = query[k];
    __syncthreads();
    float acc = bq[t];
    for (int k = 0; k < SBERT; k++) acc += qs[k] * Wq[k * HID + t];
    qout[t] = acc;
    qout2[t] = acc;
}

__global__ void scores_kern(const float* __restrict__ emb, const float* __restrict__ q,
                            float* __restrict__ sc) {
    __shared__ float qs[HID];
    int t = threadIdx.x;
    if (t < HID) qs[t] = q[t];
    __syncthreads();
    int w = t >> 5, lane = t & 31;
    int row = blockIdx.x * 8 + w;
    if (row >= NJ) return;
    float4 v = ((const float4*)(emb + (size_t)row * HID))[lane];
    float s = v.x * qs[lane * 4] + v.y * qs[lane * 4 + 1] + v.z * qs[lane * 4 + 2] +
              v.w * qs[lane * 4 + 3];
    s = wred(s);
    if (lane == 0) sc[row] = s;
}

// ---------------- launcher ----------------
extern "C" void kernel_launch(void* const* d_in, const int* in_sizes, int n_in,
                              void* d_out, int out_size) {
    const float* x_job = (const float*)d_in[0];
    const float* x_skill = (const float*)d_in[1];
    const int* js_s = (const int*)d_in[2];
    const int* js_d = (const int*)d_in[3];
    const int* sj_s = (const int*)d_in[4];
    const int* sj_d = (const int*)d_in[5];
    const int* ss_s = (const int*)d_in[6];
    const int* ss_d = (const int*)d_in[7];
    const float* query = (const float*)d_in[8];
    const float* W0j = (const float*)d_in[9];
    const float* b0j = (const float*)d_in[10];
    const float* g0j = (const float*)d_in[11];
    const float* be0j = (const float*)d_in[12];
    const float* W0s = (const float*)d_in[13];
    const float* b0s = (const float*)d_in[14];
    const float* g0s = (const float*)d_in[15];
    const float* be0s = (const float*)d_in[16];
    const float* gWs = (const float*)d_in[17];
    const float* gWd = (const float*)d_in[18];
    const float* gas = (const float*)d_in[19];
    const float* gad = (const float*)d_in[20];
    const float* gb = (const float*)d_in[21];
    const float* iW = (const float*)d_in[22];
    const float* ib = (const float*)d_in[23];
    const float* Wjf = (const float*)d_in[24];
    const float* bjf = (const float*)d_in[25];
    const float* Wq = (const float*)d_in[26];
    const float* bq = (const float*)d_in[27];

    float* out = (float*)d_out;
    float* scores = out;                // [NJ]
    float* emb = out + NJ;              // [NJ, 128]
    float* qout = out + NJ + NJ * HID;  // [128]

    float *p_xj, *p_xs, *p_hs, *p_oj, *p_os, *p_als, *p_ald, *p_wde, *p_q;
    int *p_cnt, *p_cur, *p_rpjs, *p_rpss, *p_rpsj, *p_csjs, *p_csss, *p_cssj;
    cudaGetSymbolAddress((void**)&p_xj, g_xj);
    cudaGetSymbolAddress((void**)&p_xs, g_xs);
    cudaGetSymbolAddress((void**)&p_hs, g_hs);
    cudaGetSymbolAddress((void**)&p_oj, g_oj);
    cudaGetSymbolAddress((void**)&p_os, g_os);
    cudaGetSymbolAddress((void**)&p_als, g_als);
    cudaGetSymbolAddress((void**)&p_ald, g_ald);
    cudaGetSymbolAddress((void**)&p_wde, g_wdeff);
    cudaGetSymbolAddress((void**)&p_q, g_q);
    cudaGetSymbolAddress((void**)&p_cnt, g_cnt);
    cudaGetSymbolAddress((void**)&p_cur, g_cur);
    cudaGetSymbolAddress((void**)&p_rpjs, g_rp_js);
    cudaGetSymbolAddress((void**)&p_rpss, g_rp_ss);
    cudaGetSymbolAddress((void**)&p_rpsj, g_rp_sj);
    cudaGetSymbolAddress((void**)&p_csjs, g_cs_js);
    cudaGetSymbolAddress((void**)&p_csss, g_cs_ss);
    cudaGetSymbolAddress((void**)&p_cssj, g_cs_sj);

    dim3 blk(32, 8);

    // --- CSR build (3 relations) ---
    auto build_csr = [&](const int* src, const int* dst, int E, int Esl, int Ndst,
                         int* rowptr, int* csrsrc) {
        cudaMemsetAsync(p_cnt, 0, Ndst * sizeof(int));
        count_k<<<(Esl + 255) / 256, 256>>>(dst, E, Esl, p_cnt);
        scan_k<<<1, 1024>>>(p_cnt, rowptr, p_cur, Ndst);
        fill_k<<<(Esl + 255) / 256, 256>>>(src, dst, E, Esl, p_cur, csrsrc);
    };
    build_csr(js_s, js_d, EJS, EJS, NS, p_rpjs, p_csjs);
    build_csr(ss_s, ss_d, ESS, ESS2, NS, p_rpss, p_csss);
    build_csr(sj_s, sj_d, ESJ, ESJ, NJ, p_rpsj, p_cssj);

    // --- contracted dst weights for all 6 (layer, relation) pairs ---
    wdeff_k<<<6, 256>>>(gWd, gad, p_wde);

    // --- initial per-type lin + LN + relu ---
    gemm_k<EPI_LN_RELU><<<dim3((NJ + 31) / 32, 1), blk>>>(
        x_job, SBERT, W0j, HID, p_xj, HID, NJ, SBERT, b0j, g0j, be0j, nullptr, nullptr);
    gemm_k<EPI_LN_RELU><<<dim3((NS + 31) / 32, 1), blk>>>(
        x_skill, SBERT, W0s, HID, p_xs, HID, NS, SBERT, b0s, g0s, be0s, nullptr, nullptr);

    auto rel = [&](int L, int r, const float* xsrc, int Nsrc, const float* xdst, int Ndst,
                   const int* rowptr, const int* csrsrc, float* outbuf,
                   const float* bias1, const float* bias2, bool write) {
        size_t wofs = (size_t)(L * 3 + r) * HID * HH;
        const float* Ws = gWs + wofs;
        const float* as_v = gas + (size_t)(L * 3 + r) * NH * HID;
        gemm_k<EPI_ALPHA_STORE><<<dim3((Nsrc + 31) / 32, NH), blk>>>(
            xsrc, HID, Ws, HH, p_hs, HH, Nsrc, HID, nullptr, nullptr, nullptr, as_v, p_als);
        alpha_dst_k<<<(Ndst + 7) / 8, blk>>>(xdst, p_wde + (L * 3 + r) * HH, p_ald, Ndst);
        if (write)
            gat_gather<true><<<(Ndst + 7) / 8, blk>>>(rowptr, csrsrc, p_als, p_ald, p_hs,
                                                      bias1, bias2, outbuf, Ndst);
        else
            gat_gather<false><<<(Ndst + 7) / 8, blk>>>(rowptr, csrsrc, p_als, p_ald, p_hs,
                                                       nullptr, nullptr, outbuf, Ndst);
    };

    for (int L = 0; L < 2; L++) {
        const float* b_js = gb + (size_t)(L * 3 + 0) * HH;
        const float* b_sj = gb + (size_t)(L * 3 + 1) * HH;
        const float* b_ss = gb + (size_t)(L * 3 + 2) * HH;

        // o_s = js_gather (writes b_js + b_ss) + ss_gather (accumulates)
        rel(L, 0, p_xj, NJ, p_xs, NS, p_rpjs, p_csjs, p_os, b_js, b_ss, true);
        rel(L, 2, p_xs, NS, p_xs, NS, p_rpss, p_csss, p_os, nullptr, nullptr, false);
        // o_j = sj_gather (writes b_sj)
        rel(L, 1, p_xs, NS, p_xj, NJ, p_rpsj, p_cssj, p_oj, b_sj, nullptr, true);

        // inter linears + relu
        gemm_k<EPI_BIAS_RELU><<<dim3((NJ + 31) / 32, 1), blk>>>(
            p_oj, HH, iW + (size_t)(L * 2 + 0) * HH * HID, HID, p_xj, HID, NJ, HH,
            ib + (size_t)(L * 2 + 0) * HID, nullptr, nullptr, nullptr, nullptr);
        gemm_k<EPI_BIAS_RELU><<<dim3((NS + 31) / 32, 1), blk>>>(
            p_os, HH, iW + (size_t)(L * 2 + 1) * HH * HID, HID, p_xs, HID, NS, HH,
            ib + (size_t)(L * 2 + 1) * HID, nullptr, nullptr, nullptr, nullptr);
    }

    // job_emb = xj @ Wjf + bjf -> directly into d_out
    gemm_k<EPI_BIAS_STORE><<<dim3((NJ + 31) / 32, 1), blk>>>(
        p_xj, HID, Wjf, HID, emb, HID, NJ, HID, bjf, nullptr, nullptr, nullptr, nullptr);
    // q = query @ Wq + bq
    qkern<<<1, 128>>>(query, Wq, bq, qout, p_q);
    // scores = job_emb @ q
    scores_kern<<<(NJ + 7) / 8, 256>>>(emb, p_q, scores);
}

// round 5
// speedup vs baseline: 2.6686x; 1.3139x over previous
#include <cuda_runtime.h>
#include <math.h>

#define NJ 30000
#define NS 12000
#define EJS 300000
#define ESJ 300000
#define ESS 150000
#define ESS2 (ESS + NS)   // + self loops = 162000
#define ETOT (EJS + ESS2 + ESJ)
#define SBERT 384
#define HID 128
#define NH 2
#define HH (NH * HID)     // 256
#define NCNT (2 * NS + NJ)

typedef unsigned long long ull;

// ---------------- scratch (allocation-free: __device__ globals) ----------------
__device__ __align__(16) float g_xj[NJ * HID];
__device__ __align__(16) float g_xs[NS * HID];
__device__ __align__(16) float g_hs[NJ * HH];
__device__ __align__(16) float g_oj[NJ * HH];
__device__ __align__(16) float g_os[NS * HH];
__device__ __align__(16) float g_als[NJ * NH];
__device__ __align__(16) float g_ald[NJ * NH];
__device__ __align__(16) float g_wdeff[6 * HID * NH];
__device__ __align__(16) float g_q[HID];
// CSR
__device__ int g_cnt2[NCNT];
__device__ int g_cur2[NCNT];
__device__ int g_rp_js[NS + 1];
__device__ int g_rp_ss[NS + 1];
__device__ int g_rp_sj[NJ + 1];
__device__ int g_cs_js[EJS];
__device__ int g_cs_ss[ESS2];
__device__ int g_cs_sj[ESJ];

// ---------------- helpers ----------------
__device__ __forceinline__ float wred(float v) {
#pragma unroll
    for (int o = 16; o > 0; o >>= 1) v += __shfl_xor_sync(0xffffffffu, v, o);
    return v;
}

#define FMA2(c, a, b) asm("fma.rn.f32x2 %0, %1, %2, %0;" : "+l"(c) : "l"(a), "l"(b))

__device__ __forceinline__ ull dup2(float x) {
    unsigned u = __float_as_uint(x);
    ull r;
    asm("mov.b64 %0, {%1, %1};" : "=l"(r) : "r"(u));
    return r;
}
__device__ __forceinline__ float ulo(ull u) { return __uint_as_float((unsigned)u); }
__device__ __forceinline__ float uhi(ull u) { return __uint_as_float((unsigned)(u >> 32)); }

// ---------------- f32x2 tiled SGEMM v2: FMA-pipe-bound layout ----------------
// Block (32,8) = 256 thr; tile 64 rows x 128 cols; thread: rows ty*8..ty*8+7,
// cols tx*4..tx*4+3. Row PAIRS live in the f32x2 lanes; B duplicated in regs.
// Per warp-k-iter: 2 LDS.128 bcast (A, 2 phases) + 1 LDS.128 (B, 4 phases)
// + 4 mov.b64 + 16 FFMA2 -> fma-pipe is the binder (68 TF/s ceiling).
#define EPI_BIAS_RELU 1
#define EPI_LN_RELU 2
#define EPI_ALPHA_STORE 3
#define EPI_BIAS_STORE 5

template <int EPI>
__global__ void gemm_k(const float* __restrict__ A, int lda,
                       const float* __restrict__ B0, int ldb,
                       float* __restrict__ C0, int ldc,
                       int N, int K,
                       const float* __restrict__ bias,
                       const float* __restrict__ gamma, const float* __restrict__ beta,
                       const float* __restrict__ avec0, float* __restrict__ alpha) {
    const int head = blockIdx.y;
    const float* B = B0 + head * HID;
    float* C = C0 ? (C0 + head * HID) : C0;

    const int tx = threadIdx.x, ty = threadIdx.y;
    const int tid = ty * 32 + tx;
    const int row0 = blockIdx.x * 64;

    __shared__ __align__(16) float As[16][68];        // [k][row], pad 68 (272B, 16B-aligned)
    __shared__ __align__(16) float4 Bs[16][32];       // [k][col4]

    ull acc[4][4];  // [row-pair p][col j]; pair p = rows (2p, 2p+1)
#pragma unroll
    for (int p = 0; p < 4; p++)
#pragma unroll
        for (int j = 0; j < 4; j++) acc[p][j] = 0ull;

    const int arow = tid >> 2;          // 0..63
    const int kc = (tid & 3) * 4;       // 0,4,8,12
    const bool arow_ok = (row0 + arow) < N;
    const float* Aptr = A + (size_t)(row0 + arow) * lda + kc;

    for (int k0 = 0; k0 < K; k0 += 16) {
        // A tile: 64 rows x 16 k (coalesced float4 per thread, transpose via smem)
        float4 av = arow_ok ? *(const float4*)(Aptr + k0) : make_float4(0.f, 0.f, 0.f, 0.f);
        As[kc + 0][arow] = av.x;
        As[kc + 1][arow] = av.y;
        As[kc + 2][arow] = av.z;
        As[kc + 3][arow] = av.w;
        // B tile: 16 x 128 (2 float4 per thread)
#pragma unroll
        for (int l = 0; l < 2; l++) {
            int idx = tid + l * 256;
            int br = idx >> 5, bc = idx & 31;
            Bs[br][bc] = *(const float4*)(B + (size_t)(k0 + br) * ldb + bc * 4);
        }
        __syncthreads();
#pragma unroll
        for (int k = 0; k < 16; k++) {
            float4 a0 = *(const float4*)&As[k][ty * 8];      // rows 0..3 (2 ull pairs)
            float4 a1 = *(const float4*)&As[k][ty * 8 + 4];  // rows 4..7
            float4 bv = Bs[k][tx];
            ull ap0 = *(ull*)&a0.x, ap1 = *(ull*)&a0.z;
            ull ap2 = *(ull*)&a1.x, ap3 = *(ull*)&a1.z;
            ull b0 = dup2(bv.x), b1 = dup2(bv.y), b2 = dup2(bv.z), b3 = dup2(bv.w);
            FMA2(acc[0][0], ap0, b0); FMA2(acc[0][1], ap0, b1);
            FMA2(acc[0][2], ap0, b2); FMA2(acc[0][3], ap0, b3);
            FMA2(acc[1][0], ap1, b0); FMA2(acc[1][1], ap1, b1);
            FMA2(acc[1][2], ap1, b2); FMA2(acc[1][3], ap1, b3);
            FMA2(acc[2][0], ap2, b0); FMA2(acc[2][1], ap2, b1);
            FMA2(acc[2][2], ap2, b2); FMA2(acc[2][3], ap2, b3);
            FMA2(acc[3][0], ap3, b0); FMA2(acc[3][1], ap3, b1);
            FMA2(acc[3][2], ap3, b2); FMA2(acc[3][3], ap3, b3);
        }
        __syncthreads();
    }

    const int c0 = tx * 4;
    // --------- epilogue ---------
    if (EPI == EPI_LN_RELU) {
        float4 bi = *(const float4*)&bias[c0];
        float4 ga = *(const float4*)&gamma[c0];
        float4 be = *(const float4*)&beta[c0];
#pragma unroll
        for (int i = 0; i < 8; i++) {
            int grow = row0 + ty * 8 + i;
            int p = i >> 1;
            float v0, v1, v2, v3;
            if (i & 1) {
                v0 = uhi(acc[p][0]); v1 = uhi(acc[p][1]);
                v2 = uhi(acc[p][2]); v3 = uhi(acc[p][3]);
            } else {
                v0 = ulo(acc[p][0]); v1 = ulo(acc[p][1]);
                v2 = ulo(acc[p][2]); v3 = ulo(acc[p][3]);
            }
            v0 += bi.x; v1 += bi.y; v2 += bi.z; v3 += bi.w;
            float s = v0 + v1 + v2 + v3;
            float s2 = v0 * v0 + v1 * v1 + v2 * v2 + v3 * v3;
            s = wred(s); s2 = wred(s2);
            float mu = s * (1.0f / 128.0f);
            float var = s2 * (1.0f / 128.0f) - mu * mu;
            float rs = rsqrtf(var + 1e-5f);
            if (grow < N) {
                float4 o;
                o.x = fmaxf((v0 - mu) * rs * ga.x + be.x, 0.f);
                o.y = fmaxf((v1 - mu) * rs * ga.y + be.y, 0.f);
                o.z = fmaxf((v2 - mu) * rs * ga.z + be.z, 0.f);
                o.w = fmaxf((v3 - mu) * rs * ga.w + be.w, 0.f);
                *(float4*)(C + (size_t)grow * ldc + c0) = o;
            }
        }
    } else if (EPI == EPI_ALPHA_STORE) {
        float4 avv = *(const float4*)&(avec0 + head * HID)[c0];
#pragma unroll
        for (int i = 0; i < 8; i++) {
            int grow = row0 + ty * 8 + i;
            int p = i >> 1;
            float v0, v1, v2, v3;
            if (i & 1) {
                v0 = uhi(acc[p][0]); v1 = uhi(acc[p][1]);
                v2 = uhi(acc[p][2]); v3 = uhi(acc[p][3]);
            } else {
                v0 = ulo(acc[p][0]); v1 = ulo(acc[p][1]);
                v2 = ulo(acc[p][2]); v3 = ulo(acc[p][3]);
            }
            float s = v0 * avv.x + v1 * avv.y + v2 * avv.z + v3 * avv.w;
            s = wred(s);
            if (grow < N) {
                *(float4*)(C + (size_t)grow * ldc + c0) = make_float4(v0, v1, v2, v3);
                if (tx == 0) alpha[grow * NH + head] = s;
            }
        }
    } else {  // EPI_BIAS_RELU / EPI_BIAS_STORE
        float4 bi = *(const float4*)&bias[c0];
#pragma unroll
        for (int i = 0; i < 8; i++) {
            int grow = row0 + ty * 8 + i;
            if (grow >= N) continue;
            int p = i >> 1;
            float v0, v1, v2, v3;
            if (i & 1) {
                v0 = uhi(acc[p][0]); v1 = uhi(acc[p][1]);
                v2 = uhi(acc[p][2]); v3 = uhi(acc[p][3]);
            } else {
                v0 = ulo(acc[p][0]); v1 = ulo(acc[p][1]);
                v2 = ulo(acc[p][2]); v3 = ulo(acc[p][3]);
            }
            v0 += bi.x; v1 += bi.y; v2 += bi.z; v3 += bi.w;
            if (EPI == EPI_BIAS_RELU) {
                v0 = fmaxf(v0, 0.f); v1 = fmaxf(v1, 0.f);
                v2 = fmaxf(v2, 0.f); v3 = fmaxf(v3, 0.f);
            }
            *(float4*)(C + (size_t)grow * ldc + c0) = make_float4(v0, v1, v2, v3);
        }
    }
}

// ---------------- merged CSR build for all 3 relations ----------------
// cnt/cursor regions: [0,NS)=js, [NS,2NS)=ss(+loops), [2NS,2NS+NJ)=sj
__global__ void count3_k(const int* __restrict__ jsd, const int* __restrict__ ssd,
                         const int* __restrict__ sjd, int* __restrict__ cnt) {
    int i = blockIdx.x * blockDim.x + threadIdx.x;
    if (i >= ETOT) return;
    int d;
    if (i < EJS) {
        d = jsd[i];
    } else if (i < EJS + ESS2) {
        int j = i - EJS;
        d = NS + (j < ESS ? ssd[j] : j - ESS);
    } else {
        d = 2 * NS + sjd[i - EJS - ESS2];
    }
    atomicAdd(&cnt[d], 1);
}

__global__ void scan3_k(const int* __restrict__ cnt, int* __restrict__ cur,
                        int* __restrict__ rp_js, int* __restrict__ rp_ss,
                        int* __restrict__ rp_sj) {
    const int b = blockIdx.x;
    const int n = (b == 2) ? NJ : NS;
    const int off = (b == 0) ? 0 : (b == 1) ? NS : 2 * NS;
    int* rowptr = (b == 0) ? rp_js : (b == 1) ? rp_ss : rp_sj;
    const int* c = cnt + off;
    int* cu = cur + off;

    __shared__ int wsum[32];
    __shared__ int carry_s;
    int tid = threadIdx.x, lane = tid & 31, wid = tid >> 5;
    if (tid == 0) carry_s = 0;
    __syncthreads();
    for (int base = 0; base < n; base += 1024) {
        int idx = base + tid;
        int v = idx < n ? c[idx] : 0;
        int x = v;
#pragma unroll
        for (int o = 1; o < 32; o <<= 1) {
            int y = __shfl_up_sync(0xffffffffu, x, o);
            if (lane >= o) x += y;
        }
        if (lane == 31) wsum[wid] = x;
        __syncthreads();
        if (wid == 0) {
            int s = wsum[lane];
#pragma unroll
            for (int o = 1; o < 32; o <<= 1) {
                int y = __shfl_up_sync(0xffffffffu, s, o);
                if (lane >= o) s += y;
            }
            wsum[lane] = s;
        }
        __syncthreads();
        int carry = carry_s;
        int excl = carry + (wid ? wsum[wid - 1] : 0) + x - v;
        if (idx < n) { rowptr[idx] = excl; cu[idx] = excl; }
        __syncthreads();
        if (tid == 0) carry_s = carry + wsum[31];
        __syncthreads();
    }
    if (tid == 0) rowptr[n] = carry_s;
}

__global__ void fill3_k(const int* __restrict__ jss, const int* __restrict__ jsd,
                        const int* __restrict__ sss, const int* __restrict__ ssd,
                        const int* __restrict__ sjs, const int* __restrict__ sjd,
                        int* __restrict__ cur, int* __restrict__ cs_js,
                        int* __restrict__ cs_ss, int* __restrict__ cs_sj) {
    int i = blockIdx.x * blockDim.x + threadIdx.x;
    if (i >= ETOT) return;
    int d, s;
    int* cs;
    int doff;
    if (i < EJS) {
        d = jsd[i]; s = jss[i]; cs = cs_js; doff = 0;
    } else if (i < EJS + ESS2) {
        int j = i - EJS;
        if (j < ESS) { d = ssd[j]; s = sss[j]; } else { d = j - ESS; s = j - ESS; }
        cs = cs_ss; doff = NS;
    } else {
        int j = i - EJS - ESS2;
        d = sjd[j]; s = sjs[j]; cs = cs_sj; doff = 2 * NS;
    }
    int p = atomicAdd(&cur[doff + d], 1);
    cs[p] = s;
}

// ---------------- dst-alpha: ald = x_dst @ wd_eff ([Nd,128]@[128,2]) ----------------
__global__ void wdeff_k(const float* __restrict__ Wd, const float* __restrict__ ad,
                        float* __restrict__ wdeff) {
    int rel = blockIdx.x;  // 0..5
    int k = threadIdx.x >> 1, h = threadIdx.x & 1;
    const float* W = Wd + ((size_t)rel * HID + k) * HH + h * HID;
    const float* a = ad + (size_t)(rel * NH + h) * HID;
    float s = 0.f;
    for (int c = 0; c < HID; c++) s += W[c] * a[c];
    wdeff[rel * HH + k * 2 + h] = s;
}

__global__ void alpha_dst_k(const float* __restrict__ x, const float* __restrict__ wdeff,
                            float* __restrict__ ald, int N) {
    __shared__ float2 ws[HID];
    int tx = threadIdx.x, ty = threadIdx.y;
    int tid = ty * 32 + tx;
    if (tid < HID) ws[tid] = *(const float2*)&wdeff[tid * 2];
    __syncthreads();
    int d = blockIdx.x * 8 + ty;
    if (d >= N) return;
    float4 v = ((const float4*)(x + (size_t)d * HID))[tx];
    float2 w0 = ws[tx * 4], w1 = ws[tx * 4 + 1], w2 = ws[tx * 4 + 2], w3 = ws[tx * 4 + 3];
    float s0 = v.x * w0.x + v.y * w1.x + v.z * w2.x + v.w * w3.x;
    float s1 = v.x * w0.y + v.y * w1.y + v.z * w2.y + v.w * w3.y;
    s0 = wred(s0); s1 = wred(s1);
    if (tx == 0) *(float2*)&ald[d * 2] = make_float2(s0, s1);
}

// ---------------- fused GAT gather: warp per dst, single pass, no atomics ----------------
template <bool WRITE>
__global__ void gat_gather(const int* __restrict__ rowptr, const int* __restrict__ csrsrc,
                           const float* __restrict__ als, const float* __restrict__ ald,
                           const float* __restrict__ hs,
                           const float* __restrict__ bias1, const float* __restrict__ bias2,
                           float* __restrict__ out, int Ndst) {
    int lane = threadIdx.x, ty = threadIdx.y;
    int d = blockIdx.x * 8 + ty;
    if (d >= Ndst) return;
    int beg = rowptr[d], end = rowptr[d + 1];
    float ald0 = ald[d * 2], ald1 = ald[d * 2 + 1];
    float4 a0 = make_float4(0.f, 0.f, 0.f, 0.f), a1 = a0;
    float den0 = 0.f, den1 = 0.f;
#pragma unroll 2
    for (int e = beg; e < end; e++) {
        int s = csrsrc[e];
        float2 al = *(const float2*)&als[s * 2];
        float e0 = al.x + ald0; e0 = e0 > 0.f ? e0 : 0.2f * e0;
        float e1 = al.y + ald1; e1 = e1 > 0.f ? e1 : 0.2f * e1;
        float p0 = __expf(e0), p1 = __expf(e1);
        const float4* hp = (const float4*)(hs + (size_t)s * HH);
        float4 v0 = hp[lane], v1 = hp[lane + 32];
        a0.x += p0 * v0.x; a0.y += p0 * v0.y; a0.z += p0 * v0.z; a0.w += p0 * v0.w;
        a1.x += p1 * v1.x; a1.y += p1 * v1.y; a1.z += p1 * v1.z; a1.w += p1 * v1.w;
        den0 += p0; den1 += p1;
    }
    float r0 = 1.f / (den0 + 1e-16f), r1 = 1.f / (den1 + 1e-16f);
    float* o0 = out + (size_t)d * HH + lane * 4;
    float* o1 = o0 + HID;
    if (WRITE) {
        int c = lane * 4;
        float4 b0 = *(const float4*)&bias1[c];
        float4 b1 = *(const float4*)&bias1[c + HID];
        if (bias2) {
            float4 t0 = *(const float4*)&bias2[c], t1 = *(const float4*)&bias2[c + HID];
            b0.x += t0.x; b0.y += t0.y; b0.z += t0.z; b0.w += t0.w;
            b1.x += t1.x; b1.y += t1.y; b1.z += t1.z; b1.w += t1.w;
        }
        *(float4*)o0 = make_float4(b0.x + a0.x * r0, b0.y + a0.y * r0,
                                   b0.z + a0.z * r0, b0.w + a0.w * r0);
        *(float4*)o1 = make_float4(b1.x + a1.x * r1, b1.y + a1.y * r1,
                                   b1.z + a1.z * r1, b1.w + a1.w * r1);
    } else {
        float4 c0 = *(float4*)o0, c1 = *(float4*)o1;
        *(float4*)o0 = make_float4(c0.x + a0.x * r0, c0.y + a0.y * r0,
                                   c0.z + a0.z * r0, c0.w + a0.w * r0);
        *(float4*)o1 = make_float4(c1.x + a1.x * r1, c1.y + a1.y * r1,
                                   c1.z + a1.z * r1, c1.w + a1.w * r1);
    }
}

// ---------------- tail kernels ----------------
__global__ void qkern(const float* __restrict__ query, const float* __restrict__ Wq,
                      const float* __restrict__ bq, float* __restrict__ qout,
                      float* __restrict__ qout2) {
    __shared__ float qs[SBERT];
    int t = threadIdx.x;
    for (int k = t; k < SBERT; k += 128) qs[k] = query[k];
    __syncthreads();
    float acc = bq[t];
    for (int k = 0; k < SBERT; k++) acc += qs[k] * Wq[k * HID + t];
    qout[t] = acc;
    qout2[t] = acc;
}

__global__ void scores_kern(const float* __restrict__ emb, const float* __restrict__ q,
                            float* __restrict__ sc) {
    __shared__ float qs[HID];
    int t = threadIdx.x;
    if (t < HID) qs[t] = q[t];
    __syncthreads();
    int w = t >> 5, lane = t & 31;
    int row = blockIdx.x * 8 + w;
    if (row >= NJ) return;
    float4 v = ((const float4*)(emb + (size_t)row * HID))[lane];
    float s = v.x * qs[lane * 4] + v.y * qs[lane * 4 + 1] + v.z * qs[lane * 4 + 2] +
              v.w * qs[lane * 4 + 3];
    s = wred(s);
    if (lane == 0) sc[row] = s;
}

// ---------------- launcher ----------------
extern "C" void kernel_launch(void* const* d_in, const int* in_sizes, int n_in,
                              void* d_out, int out_size) {
    const float* x_job = (const float*)d_in[0];
    const float* x_skill = (const float*)d_in[1];
    const int* js_s = (const int*)d_in[2];
    const int* js_d = (const int*)d_in[3];
    const int* sj_s = (const int*)d_in[4];
    const int* sj_d = (const int*)d_in[5];
    const int* ss_s = (const int*)d_in[6];
    const int* ss_d = (const int*)d_in[7];
    const float* query = (const float*)d_in[8];
    const float* W0j = (const float*)d_in[9];
    const float* b0j = (const float*)d_in[10];
    const float* g0j = (const float*)d_in[11];
    const float* be0j = (const float*)d_in[12];
    const float* W0s = (const float*)d_in[13];
    const float* b0s = (const float*)d_in[14];
    const float* g0s = (const float*)d_in[15];
    const float* be0s = (const float*)d_in[16];
    const float* gWs = (const float*)d_in[17];
    const float* gWd = (const float*)d_in[18];
    const float* gas = (const float*)d_in[19];
    const float* gad = (const float*)d_in[20];
    const float* gb = (const float*)d_in[21];
    const float* iW = (const float*)d_in[22];
    const float* ib = (const float*)d_in[23];
    const float* Wjf = (const float*)d_in[24];
    const float* bjf = (const float*)d_in[25];
    const float* Wq = (const float*)d_in[26];
    const float* bq = (const float*)d_in[27];

    float* out = (float*)d_out;
    float* scores = out;                // [NJ]
    float* emb = out + NJ;              // [NJ, 128]
    float* qout = out + NJ + NJ * HID;  // [128]

    float *p_xj, *p_xs, *p_hs, *p_oj, *p_os, *p_als, *p_ald, *p_wde, *p_q;
    int *p_cnt, *p_cur, *p_rpjs, *p_rpss, *p_rpsj, *p_csjs, *p_csss, *p_cssj;
    cudaGetSymbolAddress((void**)&p_xj, g_xj);
    cudaGetSymbolAddress((void**)&p_xs, g_xs);
    cudaGetSymbolAddress((void**)&p_hs, g_hs);
    cudaGetSymbolAddress((void**)&p_oj, g_oj);
    cudaGetSymbolAddress((void**)&p_os, g_os);
    cudaGetSymbolAddress((void**)&p_als, g_als);
    cudaGetSymbolAddress((void**)&p_ald, g_ald);
    cudaGetSymbolAddress((void**)&p_wde, g_wdeff);
    cudaGetSymbolAddress((void**)&p_q, g_q);
    cudaGetSymbolAddress((void**)&p_cnt, g_cnt2);
    cudaGetSymbolAddress((void**)&p_cur, g_cur2);
    cudaGetSymbolAddress((void**)&p_rpjs, g_rp_js);
    cudaGetSymbolAddress((void**)&p_rpss, g_rp_ss);
    cudaGetSymbolAddress((void**)&p_rpsj, g_rp_sj);
    cudaGetSymbolAddress((void**)&p_csjs, g_cs_js);
    cudaGetSymbolAddress((void**)&p_csss, g_cs_ss);
    cudaGetSymbolAddress((void**)&p_cssj, g_cs_sj);

    dim3 blk(32, 8);

    // --- merged CSR build (4 launches total) ---
    cudaMemsetAsync(p_cnt, 0, NCNT * sizeof(int));
    count3_k<<<(ETOT + 255) / 256, 256>>>(js_d, ss_d, sj_d, p_cnt);
    scan3_k<<<3, 1024>>>(p_cnt, p_cur, p_rpjs, p_rpss, p_rpsj);
    fill3_k<<<(ETOT + 255) / 256, 256>>>(js_s, js_d, ss_s, ss_d, sj_s, sj_d,
                                         p_cur, p_csjs, p_csss, p_cssj);

    // --- contracted dst weights for all 6 (layer, relation) pairs ---
    wdeff_k<<<6, 256>>>(gWd, gad, p_wde);

    // --- initial per-type lin + LN + relu ---
    gemm_k<EPI_LN_RELU><<<dim3((NJ + 63) / 64, 1), blk>>>(
        x_job, SBERT, W0j, HID, p_xj, HID, NJ, SBERT, b0j, g0j, be0j, nullptr, nullptr);
    gemm_k<EPI_LN_RELU><<<dim3((NS + 63) / 64, 1), blk>>>(
        x_skill, SBERT, W0s, HID, p_xs, HID, NS, SBERT, b0s, g0s, be0s, nullptr, nullptr);

    auto rel = [&](int L, int r, const float* xsrc, int Nsrc, const float* xdst, int Ndst,
                   const int* rowptr, const int* csrsrc, float* outbuf,
                   const float* bias1, const float* bias2, bool write) {
        size_t wofs = (size_t)(L * 3 + r) * HID * HH;
        const float* Ws = gWs + wofs;
        const float* as_v = gas + (size_t)(L * 3 + r) * NH * HID;
        gemm_k<EPI_ALPHA_STORE><<<dim3((Nsrc + 63) / 64, NH), blk>>>(
            xsrc, HID, Ws, HH, p_hs, HH, Nsrc, HID, nullptr, nullptr, nullptr, as_v, p_als);
        alpha_dst_k<<<(Ndst + 7) / 8, blk>>>(xdst, p_wde + (L * 3 + r) * HH, p_ald, Ndst);
        if (write)
            gat_gather<true><<<(Ndst + 7) / 8, blk>>>(rowptr, csrsrc, p_als, p_ald, p_hs,
                                                      bias1, bias2, outbuf, Ndst);
        else
            gat_gather<false><<<(Ndst + 7) / 8, blk>>>(rowptr, csrsrc, p_als, p_ald, p_hs,
                                                       nullptr, nullptr, outbuf, Ndst);
    };

    for (int L = 0; L < 2; L++) {
        const float* b_js = gb + (size_t)(L * 3 + 0) * HH;
        const float* b_sj = gb + (size_t)(L * 3 + 1) * HH;
        const float* b_ss = gb + (size_t)(L * 3 + 2) * HH;

        // o_s = js_gather (writes b_js + b_ss) + ss_gather (accumulates)
        rel(L, 0, p_xj, NJ, p_xs, NS, p_rpjs, p_csjs, p_os, b_js, b_ss, true);
        rel(L, 2, p_xs, NS, p_xs, NS, p_rpss, p_csss, p_os, nullptr, nullptr, false);
        // o_j = sj_gather (writes b_sj)
        rel(L, 1, p_xs, NS, p_xj, NJ, p_rpsj, p_cssj, p_oj, b_sj, nullptr, true);

        // inter linears + relu
        gemm_k<EPI_BIAS_RELU><<<dim3((NJ + 63) / 64, 1), blk>>>(
            p_oj, HH, iW + (size_t)(L * 2 + 0) * HH * HID, HID, p_xj, HID, NJ, HH,
            ib + (size_t)(L * 2 + 0) * HID, nullptr, nullptr, nullptr, nullptr);
        gemm_k<EPI_BIAS_RELU><<<dim3((NS + 63) / 64, 1), blk>>>(
            p_os, HH, iW + (size_t)(L * 2 + 1) * HH * HID, HID, p_xs, HID, NS, HH,
            ib + (size_t)(L * 2 + 1) * HID, nullptr, nullptr, nullptr, nullptr);
    }

    // job_emb = xj @ Wjf + bjf -> directly into d_out
    gemm_k<EPI_BIAS_STORE><<<dim3((NJ + 63) / 64, 1), blk>>>(
        p_xj, HID, Wjf, HID, emb, HID, NJ, HID, bjf, nullptr, nullptr, nullptr, nullptr);
    // q = query @ Wq + bq
    qkern<<<1, 128>>>(query, Wq, bq, qout, p_q);
    // scores = job_emb @ q
    scores_kern<<<(NJ + 7) / 8, 256>>>(emb, p_q, scores);
}